// round 7
// baseline (speedup 1.0000x reference)
#include <cuda_runtime.h>
#include <cuda_bf16.h>
#include <cstdint>

#define BB 2
#define NN 2048
#define DIN 512
#define HH 8
#define FF 64
#define HF 512
#define TILES 16

__device__ float g_mapped[(size_t)BB*NN*HF];
__device__ float g_el[BB*NN*HH];
__device__ float g_er[BB*NN*HH];
__device__ float g_hout[(size_t)BB*HH*NN*FF];
__device__ __align__(16) unsigned char g_eb[(size_t)BB*NN*NN];

__device__ __forceinline__ unsigned long long pack2(float lo, float hi){
    unsigned long long r; asm("mov.b64 %0, {%1, %2};" : "=l"(r) : "f"(lo), "f"(hi)); return r;
}
#define FMA2(acc, p, v) asm("fma.rn.f32x2 %0, %1, %2, %0;" : "+l"(acc) : "l"(p), "l"(v))

__device__ __forceinline__ uint32_t smem_u32(const void* p){
    uint32_t a; asm("{ .reg .u64 t; cvta.to.shared.u64 t, %1; cvt.u32.u64 %0, t; }" : "=r"(a) : "l"(p)); return a;
}

// ---------------- kernel 1: mapped = nodes @ W (passing baseline) -------------
__global__ __launch_bounds__(256) void gemm_kernel(const float* __restrict__ A,
                                                   const float* __restrict__ Bm) {
    __shared__ float As[16][132];
    __shared__ float Bs[16][128];
    const int tid = threadIdx.x;
    const int bm = blockIdx.y * 128, bn = blockIdx.x * 128;
    const int tx = tid & 15, ty = tid >> 4;
    unsigned long long acc2[8][4];
#pragma unroll
    for (int i = 0; i < 8; i++)
#pragma unroll
        for (int j = 0; j < 4; j++) acc2[i][j] = 0ull;
    const int ar = tid >> 2, ak = (tid & 3) << 2, bk = tid >> 5, bc = (tid & 31) << 2;
    for (int k0 = 0; k0 < DIN; k0 += 16) {
        float4 a0 = *(const float4*)&A[(size_t)(bm + ar) * DIN + k0 + ak];
        float4 a1 = *(const float4*)&A[(size_t)(bm + ar + 64) * DIN + k0 + ak];
        float4 b0 = *(const float4*)&Bm[(size_t)(k0 + bk) * HF + bn + bc];
        float4 b1 = *(const float4*)&Bm[(size_t)(k0 + bk + 8) * HF + bn + bc];
        __syncthreads();
        As[ak + 0][ar] = a0.x; As[ak + 1][ar] = a0.y;
        As[ak + 2][ar] = a0.z; As[ak + 3][ar] = a0.w;
        As[ak + 0][ar + 64] = a1.x; As[ak + 1][ar + 64] = a1.y;
        As[ak + 2][ar + 64] = a1.z; As[ak + 3][ar + 64] = a1.w;
        *(float4*)&Bs[bk][bc] = b0;
        *(float4*)&Bs[bk + 8][bc] = b1;
        __syncthreads();
#pragma unroll
        for (int k = 0; k < 16; k++) {
            float4 va0 = *(const float4*)&As[k][ty * 8];
            float4 va1 = *(const float4*)&As[k][ty * 8 + 4];
            ulonglong2 vb0 = *(const ulonglong2*)&Bs[k][tx * 8];
            float av[8] = {va0.x, va0.y, va0.z, va0.w, va1.x, va1.y, va1.z, va1.w};
            unsigned long long b2[4] = {vb0.x, vb0.y, 0, 0};
            ulonglong2 vb1 = *(const ulonglong2*)&Bs[k][tx * 8 + 4];
            b2[2] = vb1.x; b2[3] = vb1.y;
#pragma unroll
            for (int i = 0; i < 8; i++) {
                unsigned long long a2 = pack2(av[i], av[i]);
#pragma unroll
                for (int jq = 0; jq < 4; jq++) FMA2(acc2[i][jq], a2, b2[jq]);
            }
        }
    }
#pragma unroll
    for (int i = 0; i < 8; i++) {
        size_t base = (size_t)(bm + ty * 8 + i) * HF + bn + tx * 8;
        ulonglong2 c0; c0.x = acc2[i][0]; c0.y = acc2[i][1];
        ulonglong2 c1; c1.x = acc2[i][2]; c1.y = acc2[i][3];
        *(ulonglong2*)&g_mapped[base]     = c0;
        *(ulonglong2*)&g_mapped[base + 4] = c1;
    }
}

// ---------------- kernel 2: el/er ---------------------------------------------
__global__ __launch_bounds__(256) void elr_kernel(const float* __restrict__ a) {
    int idx = blockIdx.x * 256 + threadIdx.x;
    if (idx >= BB * NN * HH) return;
    const float4* mp = (const float4*)&g_mapped[(size_t)idx * FF];
    const float4* al = (const float4*)a;
    const float4* ar = (const float4*)(a + FF);
    float el = 0.f, er = 0.f;
#pragma unroll
    for (int q = 0; q < FF / 4; q++) {
        float4 v = mp[q], x = al[q], y = ar[q];
        el += v.x * x.x + v.y * x.y + v.z * x.z + v.w * x.w;
        er += v.x * y.x + v.y * y.y + v.z * y.z + v.w * y.w;
    }
    g_el[idx] = el; g_er[idx] = er;
}

// ---------------- kernel 2b: pack edges int32 -> byte --------------------------
__global__ __launch_bounds__(256) void pack_edges_kernel(const int* __restrict__ e) {
    size_t base = ((size_t)blockIdx.x * 256 + threadIdx.x) * 16;
    uint32_t out[4];
#pragma unroll
    for (int w = 0; w < 4; w++) {
        int4 v = *(const int4*)(e + base + w * 4);
        out[w] = (v.x ? 1u : 0u) | ((v.y ? 1u : 0u) << 8) |
                 ((v.z ? 1u : 0u) << 16) | ((v.w ? 1u : 0u) << 24);
    }
    uint4 o; o.x = out[0]; o.y = out[1]; o.z = out[2]; o.w = out[3];
    *(uint4*)(g_eb + base) = o;
}

// ---------------- kernel 3: mma.sync (HMMA bf16) attention --------------------
// CTA = (128-i-tile, b, head-pair); warp = (head = w>>2, i-quarter q = w&3).
// D[32i x 64f] per warp in registers (fp32). P computed straight into A-frags.
// V staged [j][f] bf16 hi/lo, 128B rows, 16B-XOR swizzle; B frags via
// ldmatrix.x4.trans. fp32 = bf16_hi + bf16_lo; 3 passes/k-step.
#define SV   0          // [head][hi/lo] 4 x 16384
#define SEB  65536      // 128 rows x 144B  = 18432
#define SER  83968      // [head][128] f32 = 1024
#define SM_AT 84992

#define MMA(c, a, b0, b1) asm volatile( \
    "mma.sync.aligned.m16n8k16.row.col.f32.bf16.bf16.f32 " \
    "{%0,%1,%2,%3}, {%4,%5,%6,%7}, {%8,%9}, {%0,%1,%2,%3};" \
    : "+f"((c)[0]), "+f"((c)[1]), "+f"((c)[2]), "+f"((c)[3]) \
    : "r"((a)[0]), "r"((a)[1]), "r"((a)[2]), "r"((a)[3]), "r"(b0), "r"(b1))

#define LDSM4T(r, addr) asm volatile( \
    "ldmatrix.sync.aligned.m8n8.x4.trans.shared.b16 {%0,%1,%2,%3}, [%4];" \
    : "=r"((r)[0]), "=r"((r)[1]), "=r"((r)[2]), "=r"((r)[3]) : "r"(addr))

#define PPAIR(DH, DL, EL, ER2, EU, LACC) do{                                  \
    float e0 = (EL) + (ER2).x, e1 = (EL) + (ER2).y;                           \
    float s0 = fmaxf(e0, 0.2f * e0), s1 = fmaxf(e1, 0.2f * e1);               \
    float p0 = ((EU) & 0xFFu)   ? __expf(s0) : 0.f;                           \
    float p1 = ((EU) & 0xFF00u) ? __expf(s1) : 0.f;                           \
    (LACC) += p0 + p1;                                                        \
    uint32_t hx;                                                              \
    asm("cvt.rn.bf16x2.f32 %0, %1, %2;" : "=r"(hx) : "f"(p1), "f"(p0));       \
    float q0 = p0 - __uint_as_float(hx << 16);                                \
    float q1 = p1 - __uint_as_float(hx & 0xFFFF0000u);                        \
    uint32_t lx;                                                              \
    asm("cvt.rn.bf16x2.f32 %0, %1, %2;" : "=r"(lx) : "f"(q1), "f"(q0));       \
    (DH) = hx; (DL) = lx;                                                     \
} while(0)

__global__ __launch_bounds__(256, 1) void attn_hmma_kernel(void) {
    extern __shared__ char smem[];
    const uint32_t sb = smem_u32(smem);
    const int tid = threadIdx.x, w = tid >> 5, lane = tid & 31;
    const int b = blockIdx.y, i0 = blockIdx.x * 128, h0 = blockIdx.z * 2;
    const int hs = w >> 2, q = w & 3, ib = q * 32;
    const int g = lane >> 2, t = lane & 3;
    const int head = h0 + hs;

    float el_r[4];
#pragma unroll
    for (int k = 0; k < 4; k++)
        el_r[k] = g_el[((size_t)b*NN + i0 + ib + (k >> 1)*16 + (k & 1)*8 + g)*HH + head];

    float c[2][8][4];
    float l_acc[4] = {0.f, 0.f, 0.f, 0.f};
#pragma unroll
    for (int mi = 0; mi < 2; mi++)
#pragma unroll
        for (int ng = 0; ng < 8; ng++)
#pragma unroll
            for (int r = 0; r < 4; r++) c[mi][ng][r] = 0.f;

    // ldmatrix lane constants
    const int joff = ((lane >> 3) & 1) * 8 + (lane & 7);
    const int fmb  = (lane >> 4) * 8;
    const uint32_t sw = (uint32_t)((lane & 7) << 4);
    const uint32_t vbase = sb + SV + (uint32_t)hs * 32768;

    for (int tt = 0; tt < TILES; tt++) {
        const int j0 = tt * 128;
        __syncthreads();
        // ---- stage V both heads, hi/lo ----
        {
            const int j = tid >> 1, fh = (tid & 1) * 32;
            const uint32_t swj = (uint32_t)((j & 7) << 4);
#pragma unroll
            for (int hh = 0; hh < 2; hh++) {
                const float* src = g_mapped + ((size_t)b*NN + j0 + j)*HF + (h0 + hh)*FF + fh;
                uint32_t dsth = sb + SV + hh*32768u + (uint32_t)j*128u;
#pragma unroll
                for (int q4 = 0; q4 < 8; q4++) {
                    float4 v = *(const float4*)(src + q4*4);
                    uint32_t h01, h23, l01, l23;
                    asm("cvt.rn.bf16x2.f32 %0, %1, %2;" : "=r"(h01) : "f"(v.y), "f"(v.x));
                    asm("cvt.rn.bf16x2.f32 %0, %1, %2;" : "=r"(h23) : "f"(v.w), "f"(v.z));
                    float r0 = v.x - __uint_as_float(h01 << 16);
                    float r1 = v.y - __uint_as_float(h01 & 0xFFFF0000u);
                    float r2 = v.z - __uint_as_float(h23 << 16);
                    float r3 = v.w - __uint_as_float(h23 & 0xFFFF0000u);
                    asm("cvt.rn.bf16x2.f32 %0, %1, %2;" : "=r"(l01) : "f"(r1), "f"(r0));
                    asm("cvt.rn.bf16x2.f32 %0, %1, %2;" : "=r"(l23) : "f"(r3), "f"(r2));
                    uint32_t off = (uint32_t)(((fh + q4*4)*2)) ^ swj;
                    asm volatile("st.shared.v2.b32 [%0], {%1,%2};" :: "r"(dsth + off), "r"(h01), "r"(h23) : "memory");
                    asm volatile("st.shared.v2.b32 [%0], {%1,%2};" :: "r"(dsth + 16384u + off), "r"(l01), "r"(l23) : "memory");
                }
            }
        }
        // ---- stage edge bytes (row stride 144) ----
        {
            const int row = tid >> 1, half = tid & 1;
            const uint4* esrc = (const uint4*)(g_eb + ((size_t)b*NN + i0 + row)*NN + j0 + half*64);
            char* edst = smem + SEB + row*144 + half*64;
            uint4 e0 = esrc[0], e1 = esrc[1], e2 = esrc[2], e3 = esrc[3];
            *(uint4*)(edst)      = e0;  *(uint4*)(edst + 16) = e1;
            *(uint4*)(edst + 32) = e2;  *(uint4*)(edst + 48) = e3;
        }
        // ---- stage er both heads ----
        {
            const int hh = tid >> 7, jj = tid & 127;
            ((float*)(smem + SER))[hh*128 + jj] = g_er[((size_t)b*NN + j0 + jj)*HH + h0 + hh];
        }
        __syncthreads();

        for (int tk = 0; tk < 8; tk++) {
            const int j0k = tk * 16;
            // ---- B fragments (V) ----
            uint32_t bh[16], bl[16];
            {
                uint32_t rowb = vbase + (uint32_t)(j0k + joff)*128u;
#pragma unroll
                for (int li = 0; li < 4; li++) {
                    uint32_t off = ((uint32_t)((fmb + li*16)*2)) ^ sw;
                    LDSM4T(bh + li*4, rowb + off);
                    LDSM4T(bl + li*4, rowb + 16384u + off);
                }
            }
            // ---- A fragments (P) computed in-place ----
            float2 erA = *(const float2*)(smem + SER + hs*512 + (j0k + 2*t)*4);
            float2 erB = *(const float2*)(smem + SER + hs*512 + (j0k + 8 + 2*t)*4);
            uint32_t ah[2][4], al[2][4];
#pragma unroll
            for (int mi = 0; mi < 2; mi++) {
                uint32_t ea = sb + SEB + (uint32_t)((ib + mi*16 + g)*144 + j0k + 2*t);
                uint32_t eA0, eA1, eB0, eB1;
                asm volatile("ld.shared.u16 %0, [%1];"     : "=r"(eA0) : "r"(ea));
                asm volatile("ld.shared.u16 %0, [%1+8];"   : "=r"(eA1) : "r"(ea));
                asm volatile("ld.shared.u16 %0, [%1+1152];": "=r"(eB0) : "r"(ea));
                asm volatile("ld.shared.u16 %0, [%1+1160];": "=r"(eB1) : "r"(ea));
                PPAIR(ah[mi][0], al[mi][0], el_r[mi*2],     erA, eA0, l_acc[mi*2]);
                PPAIR(ah[mi][1], al[mi][1], el_r[mi*2 + 1], erA, eB0, l_acc[mi*2 + 1]);
                PPAIR(ah[mi][2], al[mi][2], el_r[mi*2],     erB, eA1, l_acc[mi*2]);
                PPAIR(ah[mi][3], al[mi][3], el_r[mi*2 + 1], erB, eB1, l_acc[mi*2 + 1]);
            }
            // ---- 48 HMMA ----
#pragma unroll
            for (int ng = 0; ng < 8; ng++) {
                const int bi = (ng >> 1)*4 + (ng & 1)*2;
                MMA(c[0][ng], ah[0], bh[bi], bh[bi+1]);
                MMA(c[1][ng], ah[1], bh[bi], bh[bi+1]);
                MMA(c[0][ng], ah[0], bl[bi], bl[bi+1]);
                MMA(c[1][ng], ah[1], bl[bi], bl[bi+1]);
                MMA(c[0][ng], al[0], bh[bi], bh[bi+1]);
                MMA(c[1][ng], al[1], bh[bi], bh[bi+1]);
            }
        }
    }

    // ---- epilogue: reduce l over t-lanes, normalize, store ----
    float linv[4];
#pragma unroll
    for (int k = 0; k < 4; k++) {
        float l = l_acc[k];
        l += __shfl_xor_sync(0xffffffffu, l, 1);
        l += __shfl_xor_sync(0xffffffffu, l, 2);
        linv[k] = 1.f / l;
    }
#pragma unroll
    for (int mi = 0; mi < 2; mi++)
#pragma unroll
        for (int u = 0; u < 2; u++) {
            const int row = i0 + ib + mi*16 + u*8 + g;
            float* dst = g_hout + (((size_t)b*HH + head)*NN + row)*FF + 2*t;
            const float lv = linv[mi*2 + u];
#pragma unroll
            for (int ng = 0; ng < 8; ng++) {
                float2 val;
                val.x = c[mi][ng][u*2 + 0] * lv;
                val.y = c[mi][ng][u*2 + 1] * lv;
                *(float2*)(dst + ng*8) = val;
            }
        }
}

// ---------------- kernel 4: mean over heads + sigmoid -------------------------
__global__ __launch_bounds__(256) void combine_kernel(float* __restrict__ out) {
    int idx = blockIdx.x * 256 + threadIdx.x;
    if (idx >= BB * NN * FF) return;
    int f = idx & 63;
    int bi = idx >> 6;
    int b = bi >> 11, i = bi & 2047;
    float s = 0.f;
#pragma unroll
    for (int h = 0; h < HH; h++)
        s += g_hout[(((size_t)b * HH + h) * NN + i) * FF + f];
    s *= 0.125f;
    out[idx] = 1.f / (1.f + __expf(-s));
}

// ---------------- launch ------------------------------------------------------
extern "C" void kernel_launch(void* const* d_in, const int* in_sizes, int n_in,
                              void* d_out, int out_size) {
    const float* nodes = (const float*)d_in[0];
    const int*   edges = (const int*)d_in[1];
    const float* W     = (const float*)d_in[2];
    const float* a     = (const float*)d_in[3];
    float* out = (float*)d_out;

    static int attr_set = 0;
    if (!attr_set) {
        cudaFuncSetAttribute(attn_hmma_kernel, cudaFuncAttributeMaxDynamicSharedMemorySize,
                             SM_AT);
        attr_set = 1;
    }

    dim3 ggrid(HF / 128, (BB * NN) / 128);
    gemm_kernel<<<ggrid, 256>>>(nodes, W);

    elr_kernel<<<(BB * NN * HH + 255) / 256, 256>>>(a);

    pack_edges_kernel<<<(BB * NN * NN) / (256 * 16), 256>>>(edges);

    dim3 agrid(NN / 128, BB, HH / 2);     // (16, 2, 4) = 128 CTAs
    attn_hmma_kernel<<<agrid, 256, SM_AT>>>();

    combine_kernel<<<(BB * NN * FF + 255) / 256, 256>>>(out);
}

// round 12
// speedup vs baseline: 2.4490x; 2.4490x over previous
#include <cuda_runtime.h>
#include <cuda_bf16.h>
#include <cstdint>

#define BB 2
#define NN 2048
#define DIN 512
#define HH 8
#define FF 64
#define HF 512
#define TILES 16
#define LOG2E 1.4426950408889634f

__device__ float g_mapped[(size_t)BB*NN*HF];
__device__ float g_el[BB*NN*HH];
__device__ float g_er[BB*NN*HH];
__device__ float g_hout[(size_t)BB*HH*NN*FF];
__device__ __align__(16) unsigned char g_eb[(size_t)BB*NN*NN];

__device__ __forceinline__ unsigned long long pack2(float lo, float hi){
    unsigned long long r; asm("mov.b64 %0, {%1, %2};" : "=l"(r) : "f"(lo), "f"(hi)); return r;
}
#define FMA2(acc, p, v) asm("fma.rn.f32x2 %0, %1, %2, %0;" : "+l"(acc) : "l"(p), "l"(v))

__device__ __forceinline__ uint32_t smem_u32(const void* p){
    uint32_t a; asm("{ .reg .u64 t; cvta.to.shared.u64 t, %1; cvt.u32.u64 %0, t; }" : "=r"(a) : "l"(p)); return a;
}

#define MMA(c, a, b0, b1) asm volatile( \
    "mma.sync.aligned.m16n8k16.row.col.f32.bf16.bf16.f32 " \
    "{%0,%1,%2,%3}, {%4,%5,%6,%7}, {%8,%9}, {%0,%1,%2,%3};" \
    : "+f"((c)[0]), "+f"((c)[1]), "+f"((c)[2]), "+f"((c)[3]) \
    : "r"((a)[0]), "r"((a)[1]), "r"((a)[2]), "r"((a)[3]), "r"(b0), "r"(b1))

#define LDSM4T(r, addr) asm volatile( \
    "ldmatrix.sync.aligned.m8n8.x4.trans.shared.b16 {%0,%1,%2,%3}, [%4];" \
    : "=r"((r)[0]), "=r"((r)[1]), "=r"((r)[2]), "=r"((r)[3]) : "r"(addr))

// ---------------- kernel 1: mapped = nodes @ W (proven scalar baseline) -------
__global__ __launch_bounds__(256) void gemm_kernel(const float* __restrict__ A,
                                                   const float* __restrict__ Bm) {
    __shared__ float As[16][132];
    __shared__ float Bs[16][128];
    const int tid = threadIdx.x;
    const int bm = blockIdx.y * 128, bn = blockIdx.x * 128;
    const int tx = tid & 15, ty = tid >> 4;
    unsigned long long acc2[8][4];
#pragma unroll
    for (int i = 0; i < 8; i++)
#pragma unroll
        for (int j = 0; j < 4; j++) acc2[i][j] = 0ull;
    const int ar = tid >> 2, ak = (tid & 3) << 2, bk = tid >> 5, bc = (tid & 31) << 2;
    for (int k0 = 0; k0 < DIN; k0 += 16) {
        float4 a0 = *(const float4*)&A[(size_t)(bm + ar) * DIN + k0 + ak];
        float4 a1 = *(const float4*)&A[(size_t)(bm + ar + 64) * DIN + k0 + ak];
        float4 b0 = *(const float4*)&Bm[(size_t)(k0 + bk) * HF + bn + bc];
        float4 b1 = *(const float4*)&Bm[(size_t)(k0 + bk + 8) * HF + bn + bc];
        __syncthreads();
        As[ak + 0][ar] = a0.x; As[ak + 1][ar] = a0.y;
        As[ak + 2][ar] = a0.z; As[ak + 3][ar] = a0.w;
        As[ak + 0][ar + 64] = a1.x; As[ak + 1][ar + 64] = a1.y;
        As[ak + 2][ar + 64] = a1.z; As[ak + 3][ar + 64] = a1.w;
        *(float4*)&Bs[bk][bc] = b0;
        *(float4*)&Bs[bk + 8][bc] = b1;
        __syncthreads();
#pragma unroll
        for (int k = 0; k < 16; k++) {
            float4 va0 = *(const float4*)&As[k][ty * 8];
            float4 va1 = *(const float4*)&As[k][ty * 8 + 4];
            ulonglong2 vb0 = *(const ulonglong2*)&Bs[k][tx * 8];
            float av[8] = {va0.x, va0.y, va0.z, va0.w, va1.x, va1.y, va1.z, va1.w};
            unsigned long long b2[4] = {vb0.x, vb0.y, 0, 0};
            ulonglong2 vb1 = *(const ulonglong2*)&Bs[k][tx * 8 + 4];
            b2[2] = vb1.x; b2[3] = vb1.y;
#pragma unroll
            for (int i = 0; i < 8; i++) {
                unsigned long long a2 = pack2(av[i], av[i]);
#pragma unroll
                for (int jq = 0; jq < 4; jq++) FMA2(acc2[i][jq], a2, b2[jq]);
            }
        }
    }
#pragma unroll
    for (int i = 0; i < 8; i++) {
        size_t base = (size_t)(bm + ty * 8 + i) * HF + bn + tx * 8;
        ulonglong2 c0; c0.x = acc2[i][0]; c0.y = acc2[i][1];
        ulonglong2 c1; c1.x = acc2[i][2]; c1.y = acc2[i][3];
        *(ulonglong2*)&g_mapped[base]     = c0;
        *(ulonglong2*)&g_mapped[base + 4] = c1;
    }
}

// ---------------- kernel 2: el/er (pre-scaled by log2e) ------------------------
__global__ __launch_bounds__(256) void elr_kernel(const float* __restrict__ a) {
    int idx = blockIdx.x * 256 + threadIdx.x;
    if (idx >= BB * NN * HH) return;
    const float4* mp = (const float4*)&g_mapped[(size_t)idx * FF];
    const float4* al = (const float4*)a;
    const float4* ar = (const float4*)(a + FF);
    float el = 0.f, er = 0.f;
#pragma unroll
    for (int q = 0; q < FF / 4; q++) {
        float4 v = mp[q], x = al[q], y = ar[q];
        el += v.x * x.x + v.y * x.y + v.z * x.z + v.w * x.w;
        er += v.x * y.x + v.y * y.y + v.z * y.z + v.w * y.w;
    }
    g_el[idx] = el * LOG2E;
    g_er[idx] = er * LOG2E;
}

// ---------------- kernel 2b: pack edges int32 -> byte --------------------------
__global__ __launch_bounds__(256) void pack_edges_kernel(const int* __restrict__ e) {
    size_t base = ((size_t)blockIdx.x * 256 + threadIdx.x) * 16;
    uint32_t out[4];
#pragma unroll
    for (int w = 0; w < 4; w++) {
        int4 v = *(const int4*)(e + base + w * 4);
        out[w] = (v.x ? 1u : 0u) | ((v.y ? 1u : 0u) << 8) |
                 ((v.z ? 1u : 0u) << 16) | ((v.w ? 1u : 0u) << 24);
    }
    uint4 o; o.x = out[0]; o.y = out[1]; o.z = out[2]; o.w = out[3];
    *(uint4*)(g_eb + base) = o;
}

// ---------------- kernel 3: HMMA attention -------------------------------------
// grid (NN/128=16, BB=2, HH=8) = 256 CTAs, 256 thr (8 warps), 2 CTAs/SM.
// Warp owns 16 i-rows (ib = w*16). Single-pass bf16 P/V; exp = ex2 of
// pre-scaled scores. P computed straight into mma A-fragments.
#define SV   0          // 128j x 64f bf16, 128B rows, 16B-XOR swizzle = 16384
#define SEB  16384      // 128 rows x 128B edges (row stride 144)       = 18432
#define SER  34816      // 128 f32                                      = 512
#define SM_AT 35328

#define PPAIR(DH, EL, ER2, EU, LACC) do{                                      \
    float e0 = (EL) + (ER2).x, e1 = (EL) + (ER2).y;                           \
    float s0 = fmaxf(e0, 0.2f * e0), s1 = fmaxf(e1, 0.2f * e1);               \
    float p0, p1;                                                             \
    asm("ex2.approx.f32 %0, %1;" : "=f"(p0) : "f"(s0));                       \
    asm("ex2.approx.f32 %0, %1;" : "=f"(p1) : "f"(s1));                       \
    p0 = ((EU) & 0xFFu)   ? p0 : 0.f;                                         \
    p1 = ((EU) & 0xFF00u) ? p1 : 0.f;                                         \
    (LACC) += p0 + p1;                                                        \
    asm("cvt.rn.bf16x2.f32 %0, %1, %2;" : "=r"(DH) : "f"(p1), "f"(p0));       \
} while(0)

__global__ __launch_bounds__(256) void attn_hmma_kernel(void) {
    extern __shared__ char smem[];
    const uint32_t sb = smem_u32(smem);
    const int tid = threadIdx.x, w = tid >> 5, lane = tid & 31;
    const int b = blockIdx.y, i0 = blockIdx.x * 128, head = blockIdx.z;
    const int ib = w * 16;
    const int g = lane >> 2, t = lane & 3;

    float el_r[2];
    el_r[0] = g_el[((size_t)b*NN + i0 + ib + g)*HH + head];
    el_r[1] = g_el[((size_t)b*NN + i0 + ib + 8 + g)*HH + head];

    float c[8][4];
    float l_acc[2] = {0.f, 0.f};
#pragma unroll
    for (int ng = 0; ng < 8; ng++)
#pragma unroll
        for (int r = 0; r < 4; r++) c[ng][r] = 0.f;

    const int joff = ((lane >> 3) & 1) * 8 + (lane & 7);
    const int fmb  = (lane >> 4) * 8;
    const uint32_t sw = (uint32_t)((lane & 7) << 4);

    for (int tt = 0; tt < TILES; tt++) {
        const int j0 = tt * 128;
        __syncthreads();
        {   // stage V: 128j x 64f, f32 -> bf16, swizzled 128B rows (R7 pattern)
            const int j = tid >> 1, fh = (tid & 1) * 32;
            const float* src = g_mapped + ((size_t)b*NN + j0 + j)*HF + head*FF + fh;
            const uint32_t swj = (uint32_t)((j & 7) << 4);
            char* rbase = smem + SV + j * 128;
#pragma unroll
            for (int q4 = 0; q4 < 8; q4++) {
                float4 v = *(const float4*)(src + q4*4);
                uint32_t h01, h23;
                asm("cvt.rn.bf16x2.f32 %0, %1, %2;" : "=r"(h01) : "f"(v.y), "f"(v.x));
                asm("cvt.rn.bf16x2.f32 %0, %1, %2;" : "=r"(h23) : "f"(v.w), "f"(v.z));
                uint32_t off = ((uint32_t)((fh + q4*4)*2)) ^ swj;
                asm volatile("st.shared.v2.b32 [%0], {%1,%2};"
                             :: "r"(sb + SV + (uint32_t)(j*128) + off), "r"(h01), "r"(h23) : "memory");
                (void)rbase;
            }
        }
        {   // stage edges: 128 rows x 128B (row stride 144)
            const int row = tid >> 1, half = tid & 1;
            const uint4* esrc = (const uint4*)(g_eb + ((size_t)b*NN + i0 + row)*NN + j0 + half*64);
            char* edst = smem + SEB + row*144 + half*64;
            uint4 e0 = esrc[0], e1 = esrc[1], e2 = esrc[2], e3 = esrc[3];
            *(uint4*)(edst)      = e0;  *(uint4*)(edst + 16) = e1;
            *(uint4*)(edst + 32) = e2;  *(uint4*)(edst + 48) = e3;
        }
        if (tid < 128)
            ((float*)(smem + SER))[tid] = g_er[((size_t)b*NN + j0 + tid)*HH + head];
        __syncthreads();

#pragma unroll
        for (int tk = 0; tk < 8; tk++) {
            const int j0k = tk * 16;
            float2 erA = *(const float2*)(smem + SER + (j0k + 2*t)*4);
            float2 erB = *(const float2*)(smem + SER + (j0k + 8 + 2*t)*4);
            uint32_t ah[4];
            {
                uint32_t ea = sb + SEB + (uint32_t)((ib + g)*144 + j0k + 2*t);
                uint32_t eA0, eA1, eB0, eB1;
                asm volatile("ld.shared.u16 %0, [%1];"     : "=r"(eA0) : "r"(ea));
                asm volatile("ld.shared.u16 %0, [%1+8];"   : "=r"(eA1) : "r"(ea));
                asm volatile("ld.shared.u16 %0, [%1+1152];": "=r"(eB0) : "r"(ea));
                asm volatile("ld.shared.u16 %0, [%1+1160];": "=r"(eB1) : "r"(ea));
                PPAIR(ah[0], el_r[0], erA, eA0, l_acc[0]);
                PPAIR(ah[1], el_r[1], erA, eB0, l_acc[1]);
                PPAIR(ah[2], el_r[0], erB, eA1, l_acc[0]);
                PPAIR(ah[3], el_r[1], erB, eB1, l_acc[1]);
            }
            uint32_t rowb = sb + SV + (uint32_t)(j0k + joff)*128u;
#pragma unroll
            for (int li = 0; li < 4; li++) {
                uint32_t b4[4];
                uint32_t off = ((uint32_t)((fmb + li*16)*2)) ^ sw;
                LDSM4T(b4, rowb + off);
                MMA(c[li*2],     ah, b4[0], b4[1]);
                MMA(c[li*2 + 1], ah, b4[2], b4[3]);
            }
        }
    }

    float linv[2];
#pragma unroll
    for (int k = 0; k < 2; k++) {
        float l = l_acc[k];
        l += __shfl_xor_sync(0xffffffffu, l, 1);
        l += __shfl_xor_sync(0xffffffffu, l, 2);
        linv[k] = 1.f / l;
    }
#pragma unroll
    for (int u = 0; u < 2; u++) {
        const int row = i0 + ib + u*8 + g;
        float* dst = g_hout + (((size_t)b*HH + head)*NN + row)*FF + 2*t;
        const float lv = linv[u];
#pragma unroll
        for (int ng = 0; ng < 8; ng++) {
            float2 val;
            val.x = c[ng][u*2 + 0] * lv;
            val.y = c[ng][u*2 + 1] * lv;
            *(float2*)(dst + ng*8) = val;
        }
    }
}

// ---------------- kernel 4: mean over heads + sigmoid --------------------------
__global__ __launch_bounds__(256) void combine_kernel(float* __restrict__ out) {
    int idx = blockIdx.x * 256 + threadIdx.x;
    if (idx >= BB * NN * FF) return;
    int f = idx & 63;
    int bi = idx >> 6;
    int b = bi >> 11, i = bi & 2047;
    float s = 0.f;
#pragma unroll
    for (int h = 0; h < HH; h++)
        s += g_hout[(((size_t)b * HH + h) * NN + i) * FF + f];
    s *= 0.125f;
    out[idx] = 1.f / (1.f + __expf(-s));
}

// ---------------- launch -------------------------------------------------------
extern "C" void kernel_launch(void* const* d_in, const int* in_sizes, int n_in,
                              void* d_out, int out_size) {
    const float* nodes = (const float*)d_in[0];
    const int*   edges = (const int*)d_in[1];
    const float* W     = (const float*)d_in[2];
    const float* a     = (const float*)d_in[3];
    float* out = (float*)d_out;

    dim3 ggrid(HF / 128, (BB * NN) / 128);   // (4, 32)
    gemm_kernel<<<ggrid, 256>>>(nodes, W);

    elr_kernel<<<(BB * NN * HH + 255) / 256, 256>>>(a);

    pack_edges_kernel<<<(BB * NN * NN) / (256 * 16), 256>>>(edges);

    dim3 agrid(NN / 128, BB, HH);            // (16, 2, 8) = 256 CTAs
    attn_hmma_kernel<<<agrid, 256, SM_AT>>>();

    combine_kernel<<<(BB * NN * FF + 255) / 256, 256>>>(out);
}

// round 13
// speedup vs baseline: 3.2360x; 1.3214x over previous
#include <cuda_runtime.h>
#include <cuda_bf16.h>
#include <cstdint>

#define BB 2
#define NN 2048
#define DIN 512
#define HH 8
#define FF 64
#define HF 512
#define TILES 16
#define LOG2E 1.4426950408889634f

__device__ __nv_bfloat16 g_nodes_bf[(size_t)BB*NN*DIN];
__device__ __nv_bfloat16 g_w_bf[DIN*HF];
__device__ float g_mapped[(size_t)BB*NN*HF];
__device__ float g_el[BB*NN*HH];
__device__ float g_er[BB*NN*HH];
__device__ float g_hout[(size_t)BB*HH*NN*FF];
__device__ __align__(16) unsigned char g_eb[(size_t)BB*NN*NN];

__device__ __forceinline__ uint32_t smem_u32(const void* p){
    uint32_t a; asm("{ .reg .u64 t; cvta.to.shared.u64 t, %1; cvt.u32.u64 %0, t; }" : "=r"(a) : "l"(p)); return a;
}

#define MMA(c, a, b0, b1) asm volatile( \
    "mma.sync.aligned.m16n8k16.row.col.f32.bf16.bf16.f32 " \
    "{%0,%1,%2,%3}, {%4,%5,%6,%7}, {%8,%9}, {%0,%1,%2,%3};" \
    : "+f"((c)[0]), "+f"((c)[1]), "+f"((c)[2]), "+f"((c)[3]) \
    : "r"((a)[0]), "r"((a)[1]), "r"((a)[2]), "r"((a)[3]), "r"(b0), "r"(b1))

#define LDSM4(r, addr) asm volatile( \
    "ldmatrix.sync.aligned.m8n8.x4.shared.b16 {%0,%1,%2,%3}, [%4];" \
    : "=r"((r)[0]), "=r"((r)[1]), "=r"((r)[2]), "=r"((r)[3]) : "r"(addr))

#define LDSM4T(r, addr) asm volatile( \
    "ldmatrix.sync.aligned.m8n8.x4.trans.shared.b16 {%0,%1,%2,%3}, [%4];" \
    : "=r"((r)[0]), "=r"((r)[1]), "=r"((r)[2]), "=r"((r)[3]) : "r"(addr))

// ---------------- f32 -> bf16 input packs --------------------------------------
__global__ __launch_bounds__(256) void cvt_nodes_kernel(const float4* __restrict__ src) {
    int i = blockIdx.x * 256 + threadIdx.x;
    float4 v = src[i];
    uint2 o;
    asm("cvt.rn.bf16x2.f32 %0, %1, %2;" : "=r"(o.x) : "f"(v.y), "f"(v.x));
    asm("cvt.rn.bf16x2.f32 %0, %1, %2;" : "=r"(o.y) : "f"(v.w), "f"(v.z));
    ((uint2*)g_nodes_bf)[i] = o;
}
__global__ __launch_bounds__(256) void cvt_w_kernel(const float4* __restrict__ src) {
    int i = blockIdx.x * 256 + threadIdx.x;
    float4 v = src[i];
    uint2 o;
    asm("cvt.rn.bf16x2.f32 %0, %1, %2;" : "=r"(o.x) : "f"(v.y), "f"(v.x));
    asm("cvt.rn.bf16x2.f32 %0, %1, %2;" : "=r"(o.y) : "f"(v.w), "f"(v.z));
    ((uint2*)g_w_bf)[i] = o;
}

// ---------------- GEMM: mapped = nodes @ W via HMMA bf16 (f32 out) ------------
// grid (HF/64=8, B*N/128=32); 8 warps = 4m x 2n; warp tile 32m x 32n; k-chunk 64.
__global__ __launch_bounds__(256) void gemm_hmma_kernel(void) {
    __shared__ __align__(16) char smA[16384];
    __shared__ __align__(16) char smB[8192];
    const uint32_t sa = smem_u32(smA), sbm = smem_u32(smB);
    const int tid = threadIdx.x, w = tid >> 5, lane = tid & 31;
    const int bn = blockIdx.x * 64, bm = blockIdx.y * 128;
    const int mbase = (w & 3) * 32, nbase = (w >> 2) * 32;
    const int g = lane >> 2, t = lane & 3;

    float c[2][4][4];
#pragma unroll
    for (int mi = 0; mi < 2; mi++)
#pragma unroll
        for (int ng = 0; ng < 4; ng++)
#pragma unroll
            for (int r = 0; r < 4; r++) c[mi][ng][r] = 0.f;

    const int arow0 = lane & 15, akh = lane >> 4;
    const int joff = ((lane >> 3) & 1) * 8 + (lane & 7);
    const int fmb  = (lane >> 4) * 8;
    const uint32_t swb = (uint32_t)((lane & 7) << 4);

    for (int kc = 0; kc < 8; kc++) {
        const int k0 = kc * 64;
        __syncthreads();
        {   // stage A: 128 rows x 128B, swizzled
            const int row = tid >> 1, half = tid & 1;
            const uint4* src = (const uint4*)(g_nodes_bf + (size_t)(bm + row) * DIN + k0 + half * 32);
            uint4 v0 = src[0], v1 = src[1], v2 = src[2], v3 = src[3];
            const uint32_t sw = (uint32_t)((row & 7) << 4);
            char* rbase = smA + row * 128;
            *(uint4*)(rbase + (((uint32_t)(half*64 + 0))  ^ sw)) = v0;
            *(uint4*)(rbase + (((uint32_t)(half*64 + 16)) ^ sw)) = v1;
            *(uint4*)(rbase + (((uint32_t)(half*64 + 32)) ^ sw)) = v2;
            *(uint4*)(rbase + (((uint32_t)(half*64 + 48)) ^ sw)) = v3;
        }
        {   // stage B: 64 k-rows x 128B, swizzled
            const int krow = tid >> 2, q4 = tid & 3;
            const uint4* src = (const uint4*)(g_w_bf + (size_t)(k0 + krow) * HF + bn + q4 * 16);
            uint4 v0 = src[0], v1 = src[1];
            const uint32_t sw = (uint32_t)((krow & 7) << 4);
            char* rbase = smB + krow * 128;
            *(uint4*)(rbase + (((uint32_t)(q4*32 + 0))  ^ sw)) = v0;
            *(uint4*)(rbase + (((uint32_t)(q4*32 + 16)) ^ sw)) = v1;
        }
        __syncthreads();

#pragma unroll
        for (int kk = 0; kk < 4; kk++) {
            uint32_t ah[2][4];
#pragma unroll
            for (int mi = 0; mi < 2; mi++) {
                const int arow = mbase + mi * 16 + arow0;
                uint32_t addr = sa + (uint32_t)arow * 128u +
                    (((uint32_t)(kk * 32 + akh * 16)) ^ ((uint32_t)(arow & 7) << 4));
                LDSM4(ah[mi], addr);
            }
            uint32_t rowb = sbm + (uint32_t)(kk * 16 + joff) * 128u;
#pragma unroll
            for (int li = 0; li < 2; li++) {
                uint32_t b4[4];
                uint32_t off = ((uint32_t)((nbase + fmb + li * 16) * 2)) ^ swb;
                LDSM4T(b4, rowb + off);
                MMA(c[0][li*2],     ah[0], b4[0], b4[1]);
                MMA(c[1][li*2],     ah[1], b4[0], b4[1]);
                MMA(c[0][li*2 + 1], ah[0], b4[2], b4[3]);
                MMA(c[1][li*2 + 1], ah[1], b4[2], b4[3]);
            }
        }
    }
    // epilogue: f32 out (keeps downstream identical to passing R12)
#pragma unroll
    for (int mi = 0; mi < 2; mi++)
#pragma unroll
        for (int u = 0; u < 2; u++) {
            const int row = bm + mbase + mi * 16 + u * 8 + g;
#pragma unroll
            for (int ng = 0; ng < 4; ng++) {
                const int col = bn + nbase + ng * 8 + 2 * t;
                float2 val;
                val.x = c[mi][ng][u*2 + 0];
                val.y = c[mi][ng][u*2 + 1];
                *(float2*)(g_mapped + (size_t)row * HF + col) = val;
            }
        }
}

// ---------------- el/er (pre-scaled by log2e) ----------------------------------
__global__ __launch_bounds__(256) void elr_kernel(const float* __restrict__ a) {
    int idx = blockIdx.x * 256 + threadIdx.x;
    if (idx >= BB * NN * HH) return;
    const float4* mp = (const float4*)&g_mapped[(size_t)idx * FF];
    const float4* al = (const float4*)a;
    const float4* ar = (const float4*)(a + FF);
    float el = 0.f, er = 0.f;
#pragma unroll
    for (int q = 0; q < FF / 4; q++) {
        float4 v = mp[q], x = al[q], y = ar[q];
        el += v.x * x.x + v.y * x.y + v.z * x.z + v.w * x.w;
        er += v.x * y.x + v.y * y.y + v.z * y.z + v.w * y.w;
    }
    g_el[idx] = el * LOG2E;
    g_er[idx] = er * LOG2E;
}

// ---------------- pack edges int32 -> byte -------------------------------------
__global__ __launch_bounds__(256) void pack_edges_kernel(const int* __restrict__ e) {
    size_t base = ((size_t)blockIdx.x * 256 + threadIdx.x) * 16;
    uint32_t out[4];
#pragma unroll
    for (int w = 0; w < 4; w++) {
        int4 v = *(const int4*)(e + base + w * 4);
        out[w] = (v.x ? 1u : 0u) | ((v.y ? 1u : 0u) << 8) |
                 ((v.z ? 1u : 0u) << 16) | ((v.w ? 1u : 0u) << 24);
    }
    uint4 o; o.x = out[0]; o.y = out[1]; o.z = out[2]; o.w = out[3];
    *(uint4*)(g_eb + base) = o;
}

// ---------------- attention (IDENTICAL to passing R12) -------------------------
#define SV   0
#define SEB  16384
#define SER  34816
#define SM_AT 35328

#define PPAIR(DH, EL, ER2, EU, LACC) do{                                      \
    float e0 = (EL) + (ER2).x, e1 = (EL) + (ER2).y;                           \
    float s0 = fmaxf(e0, 0.2f * e0), s1 = fmaxf(e1, 0.2f * e1);               \
    float p0, p1;                                                             \
    asm("ex2.approx.f32 %0, %1;" : "=f"(p0) : "f"(s0));                       \
    asm("ex2.approx.f32 %0, %1;" : "=f"(p1) : "f"(s1));                       \
    p0 = ((EU) & 0xFFu)   ? p0 : 0.f;                                         \
    p1 = ((EU) & 0xFF00u) ? p1 : 0.f;                                         \
    (LACC) += p0 + p1;                                                        \
    asm("cvt.rn.bf16x2.f32 %0, %1, %2;" : "=r"(DH) : "f"(p1), "f"(p0));       \
} while(0)

__global__ __launch_bounds__(256) void attn_hmma_kernel(void) {
    extern __shared__ char smem[];
    const uint32_t sb = smem_u32(smem);
    const int tid = threadIdx.x, w = tid >> 5, lane = tid & 31;
    const int b = blockIdx.y, i0 = blockIdx.x * 128, head = blockIdx.z;
    const int ib = w * 16;
    const int g = lane >> 2, t = lane & 3;

    float el_r[2];
    el_r[0] = g_el[((size_t)b*NN + i0 + ib + g)*HH + head];
    el_r[1] = g_el[((size_t)b*NN + i0 + ib + 8 + g)*HH + head];

    float c[8][4];
    float l_acc[2] = {0.f, 0.f};
#pragma unroll
    for (int ng = 0; ng < 8; ng++)
#pragma unroll
        for (int r = 0; r < 4; r++) c[ng][r] = 0.f;

    const int joff = ((lane >> 3) & 1) * 8 + (lane & 7);
    const int fmb  = (lane >> 4) * 8;
    const uint32_t sw = (uint32_t)((lane & 7) << 4);

    for (int tt = 0; tt < TILES; tt++) {
        const int j0 = tt * 128;
        __syncthreads();
        {   // stage V: 128j x 64f, f32 -> bf16, swizzled 128B rows
            const int j = tid >> 1, fh = (tid & 1) * 32;
            const float* src = g_mapped + ((size_t)b*NN + j0 + j)*HF + head*FF + fh;
            const uint32_t swj = (uint32_t)((j & 7) << 4);
#pragma unroll
            for (int q4 = 0; q4 < 8; q4++) {
                float4 v = *(const float4*)(src + q4*4);
                uint32_t h01, h23;
                asm("cvt.rn.bf16x2.f32 %0, %1, %2;" : "=r"(h01) : "f"(v.y), "f"(v.x));
                asm("cvt.rn.bf16x2.f32 %0, %1, %2;" : "=r"(h23) : "f"(v.w), "f"(v.z));
                uint32_t off = ((uint32_t)((fh + q4*4)*2)) ^ swj;
                asm volatile("st.shared.v2.b32 [%0], {%1,%2};"
                             :: "r"(sb + SV + (uint32_t)(j*128) + off), "r"(h01), "r"(h23) : "memory");
            }
        }
        {   // stage edges: 128 rows x 128B (row stride 144)
            const int row = tid >> 1, half = tid & 1;
            const uint4* esrc = (const uint4*)(g_eb + ((size_t)b*NN + i0 + row)*NN + j0 + half*64);
            char* edst = smem + SEB + row*144 + half*64;
            uint4 e0 = esrc[0], e1 = esrc[1], e2 = esrc[2], e3 = esrc[3];
            *(uint4*)(edst)      = e0;  *(uint4*)(edst + 16) = e1;
            *(uint4*)(edst + 32) = e2;  *(uint4*)(edst + 48) = e3;
        }
        if (tid < 128)
            ((float*)(smem + SER))[tid] = g_er[((size_t)b*NN + j0 + tid)*HH + head];
        __syncthreads();

#pragma unroll
        for (int tk = 0; tk < 8; tk++) {
            const int j0k = tk * 16;
            float2 erA = *(const float2*)(smem + SER + (j0k + 2*t)*4);
            float2 erB = *(const float2*)(smem + SER + (j0k + 8 + 2*t)*4);
            uint32_t ah[4];
            {
                uint32_t ea = sb + SEB + (uint32_t)((ib + g)*144 + j0k + 2*t);
                uint32_t eA0, eA1, eB0, eB1;
                asm volatile("ld.shared.u16 %0, [%1];"     : "=r"(eA0) : "r"(ea));
                asm volatile("ld.shared.u16 %0, [%1+8];"   : "=r"(eA1) : "r"(ea));
                asm volatile("ld.shared.u16 %0, [%1+1152];": "=r"(eB0) : "r"(ea));
                asm volatile("ld.shared.u16 %0, [%1+1160];": "=r"(eB1) : "r"(ea));
                PPAIR(ah[0], el_r[0], erA, eA0, l_acc[0]);
                PPAIR(ah[1], el_r[1], erA, eB0, l_acc[1]);
                PPAIR(ah[2], el_r[0], erB, eA1, l_acc[0]);
                PPAIR(ah[3], el_r[1], erB, eB1, l_acc[1]);
            }
            uint32_t rowb = sb + SV + (uint32_t)(j0k + joff)*128u;
#pragma unroll
            for (int li = 0; li < 4; li++) {
                uint32_t b4[4];
                uint32_t off = ((uint32_t)((fmb + li*16)*2)) ^ sw;
                LDSM4T(b4, rowb + off);
                MMA(c[li*2],     ah, b4[0], b4[1]);
                MMA(c[li*2 + 1], ah, b4[2], b4[3]);
            }
        }
    }

    float linv[2];
#pragma unroll
    for (int k = 0; k < 2; k++) {
        float l = l_acc[k];
        l += __shfl_xor_sync(0xffffffffu, l, 1);
        l += __shfl_xor_sync(0xffffffffu, l, 2);
        linv[k] = 1.f / l;
    }
#pragma unroll
    for (int u = 0; u < 2; u++) {
        const int row = i0 + ib + u*8 + g;
        float* dst = g_hout + (((size_t)b*HH + head)*NN + row)*FF + 2*t;
        const float lv = linv[u];
#pragma unroll
        for (int ng = 0; ng < 8; ng++) {
            float2 val;
            val.x = c[ng][u*2 + 0] * lv;
            val.y = c[ng][u*2 + 1] * lv;
            *(float2*)(dst + ng*8) = val;
        }
    }
}

// ---------------- combine: mean over heads + sigmoid ---------------------------
__global__ __launch_bounds__(256) void combine_kernel(float* __restrict__ out) {
    int idx = blockIdx.x * 256 + threadIdx.x;
    if (idx >= BB * NN * FF) return;
    int f = idx & 63;
    int bi = idx >> 6;
    int b = bi >> 11, i = bi & 2047;
    float s = 0.f;
#pragma unroll
    for (int h = 0; h < HH; h++)
        s += g_hout[(((size_t)b * HH + h) * NN + i) * FF + f];
    s *= 0.125f;
    out[idx] = 1.f / (1.f + __expf(-s));
}

// ---------------- launch -------------------------------------------------------
extern "C" void kernel_launch(void* const* d_in, const int* in_sizes, int n_in,
                              void* d_out, int out_size) {
    const float* nodes = (const float*)d_in[0];
    const int*   edges = (const int*)d_in[1];
    const float* W     = (const float*)d_in[2];
    const float* a     = (const float*)d_in[3];
    float* out = (float*)d_out;

    cvt_nodes_kernel<<<(BB*NN*DIN/4)/256, 256>>>((const float4*)nodes);
    cvt_w_kernel<<<(DIN*HF/4)/256, 256>>>((const float4*)W);

    dim3 ggrid(HF / 64, (BB * NN) / 128);    // (8, 32) = 256 CTAs
    gemm_hmma_kernel<<<ggrid, 256>>>();

    elr_kernel<<<(BB * NN * HH + 255) / 256, 256>>>(a);

    pack_edges_kernel<<<(BB * NN * NN) / (256 * 16), 256>>>(edges);

    dim3 agrid(NN / 128, BB, HH);            // (16, 2, 8) = 256 CTAs
    attn_hmma_kernel<<<agrid, 256, SM_AT>>>();

    combine_kernel<<<(BB * NN * FF + 255) / 256, 256>>>(out);
}